// round 13
// baseline (speedup 1.0000x reference)
#include <cuda_runtime.h>
#include <cuda_bf16.h>
#include <cstdint>

// ---------------------------------------------------------------------------
// BLSTM_NMC: Bayesian LSTM, B=512, S=128, H=512, IN=1, OUT=1.
// R11: persistent-kernel recurrence with smem-resident W_hh.
//   - 128 CTAs (4 M-tiles x 32 N-tiles) x 512 threads, 1 CTA/SM, all
//     co-resident -> software grid barrier between steps.
//   - B (W_hh hi/lo, permuted K-major) loaded to smem ONCE, reused 128 steps.
//   - Per step: A (h hi/lo) cp.async double-buffered in 8 chunks of K=64;
//     warp tile 32x16; 3 mma passes (hh, hl, lh) pass-major into fp32 accum;
//     epilogue recombines gates in smem, fused LSTM cell, h out as bf16 hi/lo.
//   Math identical to R10 (bf16 hi/lo split) -> same rel_err class.
// ---------------------------------------------------------------------------

#define BB 512
#define SS 128
#define HH 512
#define G4 2048

#define MT 128             // M rows per CTA
#define NTF 64             // fused cols per CTA (16 hidden x 4 gates)
#define KC 64              // k per chunk
#define NCHUNK (HH / KC)   // 8
#define PT 512             // threads
#define GRID ((BB / MT) * (G4 / NTF))   // 4 * 32 = 128

// B resident: 64 rows x 512 k bf16, row stride 1040 B (1024 + 16 pad)
#define BR_STR 1040
#define SB_LO (64 * BR_STR)            // 66560
#define A_OFF (2 * SB_LO)              // 133120
// A chunk tiles: 128 rows x 64 k bf16, row stride 144 B
#define ASTRB 144
#define A_T (MT * ASTRB)               // 18432 per (hi|lo)
#define ABUF (2 * A_T)                 // 36864 per buffer
#define SMEM_DYN (A_OFF + 2 * ABUF)    // 206848 B

// ---------------- scratch ---------------------------------------------------
__device__ __nv_bfloat16 g_Bhi[G4 * HH];   // W_hh hi, [p][k] K-major, permuted
__device__ __nv_bfloat16 g_Blo[G4 * HH];
__device__ __nv_bfloat16 g_hhi[2][BB * HH];
__device__ __nv_bfloat16 g_hlo[2][BB * HH];
__device__ float g_h32[BB * HH];
__device__ float g_c[BB * HH];
__device__ float g_WihP[G4];               // permuted
__device__ float g_biasP[G4];
__device__ float g_xm[SS * BB];            // xm[s*B + b]
__device__ unsigned g_count;               // grid barrier
__device__ volatile unsigned g_gen;

// ---------------- scalar helpers -------------------------------------------
static __device__ __forceinline__ float softplus_f(float x) {
    return (x > 20.0f) ? x : log1pf(expf(x));
}
static __device__ __forceinline__ float sigm(float x) {
    return __fdividef(1.0f, 1.0f + __expf(-x));
}
static __device__ __forceinline__ float tanh_fast(float x) {
    float e = __expf(2.0f * fabsf(x));      // may be +inf -> r = 1
    float r = 1.0f - __fdividef(2.0f, e + 1.0f);
    return copysignf(r, x);
}

// ---------------- PTX helpers (baseline sm_80-class only) -------------------
static __device__ __forceinline__ uint32_t smem_u32(const void* p) {
    uint32_t a;
    asm("{ .reg .u64 t; cvta.to.shared.u64 t, %1; cvt.u32.u64 %0, t; }"
        : "=r"(a) : "l"(p));
    return a;
}
static __device__ __forceinline__ void cp16(uint32_t dst, const void* src) {
    asm volatile("cp.async.cg.shared.global [%0], [%1], 16;"
                 :: "r"(dst), "l"(src) : "memory");
}
#define CP_COMMIT() asm volatile("cp.async.commit_group;" ::: "memory")
#define CP_WAIT1()  asm volatile("cp.async.wait_group 1;" ::: "memory")
#define CP_WAIT0()  asm volatile("cp.async.wait_group 0;" ::: "memory")

static __device__ __forceinline__ void ldsm_x4(uint32_t& r0, uint32_t& r1,
                                               uint32_t& r2, uint32_t& r3,
                                               uint32_t addr) {
    asm volatile("ldmatrix.sync.aligned.m8n8.x4.shared.b16 {%0,%1,%2,%3}, [%4];"
                 : "=r"(r0), "=r"(r1), "=r"(r2), "=r"(r3) : "r"(addr));
}
static __device__ __forceinline__ void mma_bf16(float* c, const uint32_t* a,
                                                uint32_t b0, uint32_t b1) {
    asm volatile(
        "mma.sync.aligned.m16n8k16.row.col.f32.bf16.bf16.f32 "
        "{%0,%1,%2,%3}, {%4,%5,%6,%7}, {%8,%9}, {%0,%1,%2,%3};"
        : "+f"(c[0]), "+f"(c[1]), "+f"(c[2]), "+f"(c[3])
        : "r"(a[0]), "r"(a[1]), "r"(a[2]), "r"(a[3]), "r"(b0), "r"(b1));
}

// ---------------- setup kernels --------------------------------------------
__global__ void k_init(const float* __restrict__ x, const float* __restrict__ mask_in,
                       const float* __restrict__ Wih_mu, const float* __restrict__ Wih_rho,
                       const float* __restrict__ eps_ih,
                       const float* __restrict__ b_mu, const float* __restrict__ b_rho,
                       const float* __restrict__ eps_b) {
    int idx = blockIdx.x * blockDim.x + threadIdx.x;
    if (idx == 0) { g_count = 0; g_gen = 0; }
    if (idx < BB * HH) {
        g_hhi[0][idx] = __float2bfloat16(0.0f);
        g_hlo[0][idx] = __float2bfloat16(0.0f);
        g_c[idx] = 0.0f;
    }
    if (idx < BB * SS) {
        int b = idx >> 7;                    // x is (B,S) row-major
        int s = idx & (SS - 1);
        g_xm[s * BB + b] = x[idx] * mask_in[idx];
    }
    if (idx < G4) {
        int j = idx & (HH - 1);
        int g = idx >> 9;
        int p = ((j >> 4) << 6) + (g << 4) + (j & 15);
        g_WihP[p]  = Wih_mu[idx] + softplus_f(Wih_rho[idx]) * eps_ih[idx];
        g_biasP[p] = b_mu[idx]   + softplus_f(b_rho[idx])   * eps_b[idx];
    }
}

// Sample W_hh, split bf16 hi/lo, store K-major at permuted fused col.
__global__ void k_prep_whh(const float* __restrict__ mu, const float* __restrict__ rho,
                           const float* __restrict__ eps) {
    __shared__ float tile[64][17];
    const int k0 = (blockIdx.x >> 7) * 64;
    const int n0 = (blockIdx.x & 127) * 16;
    const int tid = threadIdx.x;
    for (int s = tid; s < 64 * 16; s += 256) {
        int i = s >> 4, j = s & 15;
        int src = (k0 + i) * G4 + n0 + j;
        tile[i][j] = mu[src] + softplus_f(rho[src]) * eps[src];
    }
    __syncthreads();
    for (int s = tid; s < 16 * 64; s += 256) {
        int j = s >> 6, i = s & 63;
        int n = n0 + j;
        int g = n >> 9;
        int jb = n & (HH - 1);
        int p = ((jb >> 4) << 6) + (g << 4) + (jb & 15);
        float w = tile[i][j];
        __nv_bfloat16 hi = __float2bfloat16(w);
        g_Bhi[(size_t)p * HH + k0 + i] = hi;
        g_Blo[(size_t)p * HH + k0 + i] = __float2bfloat16(w - __bfloat162float(hi));
    }
}

// ---------------- persistent recurrence kernel ------------------------------
__global__ __launch_bounds__(PT, 1)
void k_persist() {
    extern __shared__ __align__(16) char sm[];
    __shared__ float sWih[NTF];
    __shared__ float sBias[NTF];

    const int tid = threadIdx.x;
    const int wid = tid >> 5;
    const int lid = tid & 31;
    const int bx  = blockIdx.x;                 // 0..127
    const int bm0 = (bx >> 5) * MT;             // 4 M-tiles
    const int ntile = bx & 31;                  // 32 N-tiles
    const int nc0 = ntile * NTF;                // permuted fused col base
    const int hb  = ntile * 16;                 // hidden col base

    if (tid < NTF) {
        sWih[tid]  = g_WihP[nc0 + tid];
        sBias[tid] = g_biasP[nc0 + tid];
    }

    const uint32_t sb = smem_u32(sm);

    // ---- B resident load (once): 64 rows x 64 quads, hi+lo
    for (int s = tid; s < 64 * 64; s += PT) {
        int r = s >> 6, q = s & 63;
        size_t go = (size_t)(nc0 + r) * HH + q * 8;
        uint32_t so = r * BR_STR + q * 16;
        cp16(sb + so, g_Bhi + go);
        cp16(sb + SB_LO + so, g_Blo + go);
    }
    CP_COMMIT();

    // warp layout: 4(M) x 4(N); warp tile 32x16
    const int wm = wid & 3;
    const int wn = wid >> 2;
    const int a_row = wm * 32 + (lid & 15);                 // + mt*16
    const int a_k8  = (lid >> 4) << 3;
    const int b_row = wn * 16 + (lid & 7) + ((lid >> 4) << 3);
    const int b_k8  = ((lid >> 3) & 1) << 3;

    float* Sg = (float*)(sm + A_OFF);            // [128][68] (epilogue alias)

#pragma unroll 1
    for (int t = 0; t < SS; t++) {
        const __nv_bfloat16* __restrict__ Ahi_g = g_hhi[t & 1];
        const __nv_bfloat16* __restrict__ Alo_g = g_hlo[t & 1];

        // A chunk loader: 128 rows x 8 quads (hi+lo) into buffer c&1
        auto load_A = [&](int c) {
            const int k0 = c * KC;
            const uint32_t base = sb + A_OFF + (c & 1) * ABUF;
            for (int s = tid; s < 1024; s += PT) {
                int r = s >> 3, q = s & 7;
                size_t go = (size_t)(bm0 + r) * HH + k0 + q * 8;
                uint32_t so = r * ASTRB + q * 16;
                cp16(base + so, Ahi_g + go);
                cp16(base + A_T + so, Alo_g + go);
            }
            CP_COMMIT();
        };

        float acc[2][2][4];
#pragma unroll
        for (int i = 0; i < 2; i++)
#pragma unroll
            for (int j = 0; j < 2; j++)
#pragma unroll
                for (int v = 0; v < 4; v++) acc[i][j][v] = 0.0f;

        load_A(0);

        for (int c = 0; c < NCHUNK; c++) {
            if (c + 1 < NCHUNK) load_A(c + 1);
            if (c + 1 < NCHUNK) { CP_WAIT1(); } else { CP_WAIT0(); }
            __syncthreads();

            const uint32_t abase = sb + A_OFF + (c & 1) * ABUF;
#pragma unroll
            for (int kk = 0; kk < 4; kk++) {
                const uint32_t kb = (kk * 16 + a_k8) * 2;
                uint32_t ah[2][4], al[2][4];
#pragma unroll
                for (int mt = 0; mt < 2; mt++) {
                    uint32_t ad = abase + (a_row + mt * 16) * ASTRB + kb;
                    ldsm_x4(ah[mt][0], ah[mt][1], ah[mt][2], ah[mt][3], ad);
                    ldsm_x4(al[mt][0], al[mt][1], al[mt][2], al[mt][3], ad + A_T);
                }
                const uint32_t kbb = (c * KC + kk * 16 + b_k8) * 2;
                uint32_t bh[4], bl[4];
                {
                    uint32_t bd = sb + b_row * BR_STR + kbb;
                    ldsm_x4(bh[0], bh[1], bh[2], bh[3], bd);
                    ldsm_x4(bl[0], bl[1], bl[2], bl[3], bd + SB_LO);
                }
                // pass-major: consecutive mmas hit different accumulators
#pragma unroll
                for (int mt = 0; mt < 2; mt++)
#pragma unroll
                    for (int n8 = 0; n8 < 2; n8++)
                        mma_bf16(acc[mt][n8], ah[mt], bh[2 * n8], bh[2 * n8 + 1]);
#pragma unroll
                for (int mt = 0; mt < 2; mt++)
#pragma unroll
                    for (int n8 = 0; n8 < 2; n8++)
                        mma_bf16(acc[mt][n8], ah[mt], bl[2 * n8], bl[2 * n8 + 1]);
#pragma unroll
                for (int mt = 0; mt < 2; mt++)
#pragma unroll
                    for (int n8 = 0; n8 < 2; n8++)
                        mma_bf16(acc[mt][n8], al[mt], bh[2 * n8], bh[2 * n8 + 1]);
            }
            __syncthreads();
        }

        // ---- epilogue: recombine gates in smem (aliases A buffers) --------
        const int gq  = lid >> 2;
        const int tig = lid & 3;
#pragma unroll
        for (int mt = 0; mt < 2; mt++)
#pragma unroll
            for (int n8 = 0; n8 < 2; n8++) {
                int m = wm * 32 + mt * 16 + gq;
                int n = wn * 16 + n8 * 8 + tig * 2;
                *(float2*)&Sg[m * 68 + n] =
                    make_float2(acc[mt][n8][0], acc[mt][n8][1]);
                *(float2*)&Sg[(m + 8) * 68 + n] =
                    make_float2(acc[mt][n8][2], acc[mt][n8][3]);
            }
        __syncthreads();

        // ---- LSTM cell: 128 rows x 16 hidden cols (2048 elems, 4/thread) --
        const int nb = (t + 1) & 1;
        __nv_bfloat16* __restrict__ hhin = g_hhi[nb];
        __nv_bfloat16* __restrict__ hloo = g_hlo[nb];
#pragma unroll
        for (int e = tid; e < MT * 16; e += PT) {
            int m  = e >> 4;
            int jj = e & 15;
            float xv = g_xm[t * BB + bm0 + m];
            float ig = Sg[m * 68 + jj]      + xv * sWih[jj]      + sBias[jj];
            float fg = Sg[m * 68 + 16 + jj] + xv * sWih[16 + jj] + sBias[16 + jj];
            float gg = Sg[m * 68 + 32 + jj] + xv * sWih[32 + jj] + sBias[32 + jj];
            float og = Sg[m * 68 + 48 + jj] + xv * sWih[48 + jj] + sBias[48 + jj];
            size_t idx = (size_t)(bm0 + m) * HH + hb + jj;
            float cv = g_c[idx];
            float it = sigm(ig);
            float ft = sigm(fg);
            float gt = tanh_fast(gg);
            float ot = sigm(og);
            float cn = ft * cv + it * gt;
            g_c[idx] = cn;
            float hv = ot * tanh_fast(cn);
            __nv_bfloat16 hi = __float2bfloat16(hv);
            hhin[idx] = hi;
            hloo[idx] = __float2bfloat16(hv - __bfloat162float(hi));
            if (t == SS - 1) g_h32[idx] = hv;
        }

        // ---- grid barrier (skip after last step) --------------------------
        if (t < SS - 1) {
            __threadfence();
            __syncthreads();
            if (tid == 0) {
                unsigned a = atomicAdd(&g_count, 1);
                if (a == GRID - 1) {
                    g_count = 0;
                    __threadfence();
                    g_gen = (unsigned)(t + 1);
                } else {
                    while (g_gen < (unsigned)(t + 1)) { }
                }
            }
            __syncthreads();
        }
    }
}

// ---------------- output head ----------------------------------------------
__global__ void k_final(const float* __restrict__ W_lin, const float* __restrict__ b_lin,
                        const float* __restrict__ mask_out, float* __restrict__ out) {
    int b = blockIdx.x;
    int tid = threadIdx.x;
    const float* hrow = g_h32 + (size_t)b * HH;
    const float* mrow = mask_out + (size_t)b * HH;
    float s = 0.0f;
    for (int j = tid; j < HH; j += 128)
        s += hrow[j] * mrow[j] * W_lin[j];
    __shared__ float red[128];
    red[tid] = s;
    __syncthreads();
    for (int off = 64; off > 0; off >>= 1) {
        if (tid < off) red[tid] += red[tid + off];
        __syncthreads();
    }
    if (tid == 0) out[b] = red[0] + b_lin[0];
}

// ---------------- launch ----------------------------------------------------
extern "C" void kernel_launch(void* const* d_in, const int* in_sizes, int n_in,
                              void* d_out, int out_size) {
    const float* x        = (const float*)d_in[0];
    const float* Wih_mu   = (const float*)d_in[1];
    const float* Wih_rho  = (const float*)d_in[2];
    const float* eps_ih   = (const float*)d_in[3];
    const float* Whh_mu   = (const float*)d_in[4];
    const float* Whh_rho  = (const float*)d_in[5];
    const float* eps_hh   = (const float*)d_in[6];
    const float* b_mu     = (const float*)d_in[7];
    const float* b_rho    = (const float*)d_in[8];
    const float* eps_b    = (const float*)d_in[9];
    const float* W_lin    = (const float*)d_in[10];
    const float* b_lin    = (const float*)d_in[11];
    const float* mask_in  = (const float*)d_in[12];
    const float* mask_out = (const float*)d_in[13];
    float* out = (float*)d_out;
    (void)in_sizes; (void)n_in; (void)out_size;

    cudaFuncSetAttribute(k_persist, cudaFuncAttributeMaxDynamicSharedMemorySize,
                         SMEM_DYN);

    k_init<<<(BB * HH + 255) / 256, 256>>>(x, mask_in, Wih_mu, Wih_rho, eps_ih,
                                           b_mu, b_rho, eps_b);
    k_prep_whh<<<(8 * 128), 256>>>(Whh_mu, Whh_rho, eps_hh);
    k_persist<<<GRID, PT, SMEM_DYN>>>();
    k_final<<<BB, 128>>>(W_lin, b_lin, mask_out, out);
}